// round 13
// baseline (speedup 1.0000x reference)
#include <cuda_runtime.h>
#include <cuda_fp16.h>
#include <cstdint>

#define NN 100000
#define NE 1600000
#define FIN 256
#define FH 64
#define FC 16
#define NB ((NN + 255) / 256)

typedef unsigned long long u64;

// ---- scratch (device globals) ----
__device__ float  g_dinv[NN];
__device__ int    g_hist[NN];
__device__ int    g_start[NN];
__device__ int    g_rank[NE];
__device__ int    g_csr_src[NE];
__device__ int    g_alloc;
__device__ __half g_h1h[(size_t)NN * FH];     // dinv-scaled x @ W1 (fp16)
__device__ __half g_agg1h[(size_t)NN * FH];   // relu(layer-1 out) (fp16)
__device__ __half g_h2h[(size_t)NN * FC];     // dinv-scaled agg1 @ W2 (fp16)
__device__ int    g_is64;

// ---------------------------------------------------------------
// detect edge dtype (block 0) + zero hist (all blocks)
__global__ void k_init(const void* ei) {
    int i = blockIdx.x * blockDim.x + threadIdx.x;
    if (i < NN) g_hist[i] = 0;
    if (blockIdx.x == 0 && threadIdx.x < 32) {
        const long long* p = (const long long*)ei;
        bool bad = false;
        for (int j = threadIdx.x; j < 64; j += 32) {
            long long v = p[j];
            if (v < 0 || v >= NN) bad = true;
        }
        unsigned m = __ballot_sync(0xFFFFFFFFu, bad);
        if (threadIdx.x == 0) { g_is64 = (m == 0); g_alloc = 0; }
    }
}

// indices < 2^31: for int64 (little-endian) read only the low word
__device__ __forceinline__ int load_idx(const void* ei, int which, int e) {
    if (g_is64) return ((const int*)ei)[((size_t)which * NE + e) * 2];
    else        return ((const int*)ei)[(size_t)which * NE + e];
}

// ---- CSR offsets (atomic block base) + fused h1 dinv-scaling ----
__global__ void k_starts() {
    __shared__ int sm[256];
    __shared__ int sbase;
    int t = threadIdx.x;
    int i = blockIdx.x * 256 + t;
    int h = (i < NN) ? g_hist[i] : 0;
    sm[t] = h;
    __syncthreads();
#pragma unroll
    for (int off = 1; off < 256; off <<= 1) {
        int u = (t >= off) ? sm[t - off] : 0;
        __syncthreads();
        sm[t] += u;
        __syncthreads();
    }
    if (t == 255) sbase = atomicAdd(&g_alloc, sm[255]);
    __syncthreads();
    if (i < NN) {
        int excl = sbase + sm[t] - h;
        g_start[i] = excl;
        float dv = rsqrtf((float)h + 1.0f);
        g_dinv[i] = dv;
        // scale h1 row by dinv (h1 -> h1')
        __half2 dv2 = __float2half2_rn(dv);
        uint4* row = (uint4*)&g_h1h[(size_t)i * FH];
#pragma unroll
        for (int q = 0; q < 8; q++) {
            uint4 v = row[q];
            __half2* hp = (__half2*)&v;
            hp[0] = __hmul2(hp[0], dv2);
            hp[1] = __hmul2(hp[1], dv2);
            hp[2] = __hmul2(hp[2], dv2);
            hp[3] = __hmul2(hp[3], dv2);
            row[q] = v;
        }
    }
}

// atomic-free fill: pos = start[d] + rank[e]
__global__ void k_fill(const void* __restrict__ ei) {
    int e = blockIdx.x * blockDim.x + threadIdx.x;
    if (e >= NE) return;
    int s = load_idx(ei, 0, e);
    int d = load_idx(ei, 1, e);
    int pos = g_start[d] + g_rank[e];
    g_csr_src[pos] = s;
}

// ===================================================================
// GEMM1 (+ fused degree histogram w/ rank capture): mma.sync tf32,
// cp.async double-buffered; B[k][n] stride 72 (conflict-free).
// ===================================================================
#define G1_THREADS 256
#define G1_ROWS 128
#define G1_GRID ((NN + G1_ROWS - 1) / G1_ROWS)     // 782
#define EPB ((NE + G1_GRID - 1) / G1_GRID)          // 2047
#define KT 32
#define NKT (FIN / KT)
#define A_STRIDE 36
#define A_BUF_U32 (G1_ROWS * A_STRIDE)
#define B_STRIDE 72
#define B_U32 (FIN * B_STRIDE)
#define SM1_TOTAL ((2 * A_BUF_U32 + B_U32) * 4)    // 110592 -> 2 CTAs/SM

__device__ __forceinline__ uint32_t smem_u32(const void* p) {
    uint32_t a;
    asm("{ .reg .u64 t; cvta.to.shared.u64 t, %1; cvt.u32.u64 %0, t; }" : "=r"(a) : "l"(p));
    return a;
}
__device__ __forceinline__ uint32_t cvt_tf32f(float f) {
    uint32_t u;
    asm("cvt.rna.tf32.f32 %0, %1;" : "=r"(u) : "f"(f));
    return u;
}
__device__ __forceinline__ void mma_tf32(float* c, const uint32_t* a,
                                         uint32_t b0, uint32_t b1) {
    asm volatile(
        "mma.sync.aligned.m16n8k8.row.col.f32.tf32.tf32.f32 "
        "{%0,%1,%2,%3}, {%4,%5,%6,%7}, {%8,%9}, {%0,%1,%2,%3};"
        : "+f"(c[0]), "+f"(c[1]), "+f"(c[2]), "+f"(c[3])
        : "r"(a[0]), "r"(a[1]), "r"(a[2]), "r"(a[3]), "r"(b0), "r"(b1));
}

__device__ __forceinline__ void issue_tile(uint32_t dst_base, const float* __restrict__ x,
                                           int base, int kt, int tid) {
#pragma unroll
    for (int it = 0; it < 4; it++) {
        int idx = tid + it * G1_THREADS;
        int row = idx >> 3;
        int c4 = idx & 7;
        int gr = base + row;
        int ok = (gr < NN) ? 16 : 0;
        int gs = (gr < NN) ? gr : (NN - 1);
        const float* src = x + (size_t)gs * FIN + kt * KT + c4 * 4;
        uint32_t dst = dst_base + row * (A_STRIDE * 4) + c4 * 16;
        asm volatile("cp.async.ca.shared.global [%0], [%1], 16, %2;"
                     :: "r"(dst), "l"(src), "r"(ok) : "memory");
    }
    asm volatile("cp.async.commit_group;" ::: "memory");
}

__global__ void __launch_bounds__(G1_THREADS, 2) k_gemm1(const float* __restrict__ x,
                                                         const float* __restrict__ W1,
                                                         const void* __restrict__ ei) {
    extern __shared__ uint32_t smem[];
    uint32_t* As = smem;
    uint32_t* Bs = smem + 2 * A_BUF_U32;
    uint32_t asu = smem_u32(As);

    int tid = threadIdx.x;
    int w = tid >> 5;
    int lane = tid & 31;
    int lr = lane >> 2;
    int lc = lane & 3;
    int mg = w & 3;
    int ng = w >> 2;
    int base = blockIdx.x * G1_ROWS;

    issue_tile(asu, x, base, 0, tid);

    // fused degree histogram + per-edge rank capture
    {
        int ebeg = blockIdx.x * EPB;
        int eend = min(ebeg + EPB, NE);
        for (int e = ebeg + tid; e < eend; e += G1_THREADS) {
            int d = load_idx(ei, 1, e);
            g_rank[e] = atomicAdd(&g_hist[d], 1);
        }
    }

    // stage B: W1[k][n] -> Bs[k*72 + n], STS.128 conflict-free
    {
        const float4* w4 = (const float4*)W1;
#pragma unroll
        for (int it = 0; it < 16; it++) {
            int idx = tid + it * G1_THREADS;
            int k = idx >> 4;
            int n4 = idx & 15;
            float4 v = w4[idx];
            uint4 t;
            t.x = cvt_tf32f(v.x); t.y = cvt_tf32f(v.y);
            t.z = cvt_tf32f(v.z); t.w = cvt_tf32f(v.w);
            *(uint4*)&Bs[k * B_STRIDE + n4 * 4] = t;
        }
    }

    float c[2][4][4];
#pragma unroll
    for (int m = 0; m < 2; m++)
#pragma unroll
        for (int j = 0; j < 4; j++)
#pragma unroll
            for (int i = 0; i < 4; i++) c[m][j][i] = 0.0f;

    int ar = mg * 32 + lr;

#pragma unroll
    for (int kt = 0; kt < NKT; kt++) {
        if (kt + 1 < NKT) {
            issue_tile(asu + ((kt + 1) & 1) * (A_BUF_U32 * 4), x, base, kt + 1, tid);
            asm volatile("cp.async.wait_group 1;" ::: "memory");
        } else {
            asm volatile("cp.async.wait_group 0;" ::: "memory");
        }
        __syncthreads();

        const uint32_t* A = As + (kt & 1) * A_BUF_U32;
#pragma unroll
        for (int ks = 0; ks < 4; ks++) {
            int kk = ks * 8 + lc;
            uint32_t a[8];
            a[0] = A[(ar)      * A_STRIDE + kk];
            a[1] = A[(ar + 8)  * A_STRIDE + kk];
            a[2] = A[(ar)      * A_STRIDE + kk + 4];
            a[3] = A[(ar + 8)  * A_STRIDE + kk + 4];
            a[4] = A[(ar + 16) * A_STRIDE + kk];
            a[5] = A[(ar + 24) * A_STRIDE + kk];
            a[6] = A[(ar + 16) * A_STRIDE + kk + 4];
            a[7] = A[(ar + 24) * A_STRIDE + kk + 4];
            int kg = kt * KT + ks * 8 + lc;
            const uint32_t* B0 = Bs + kg * B_STRIDE;
            const uint32_t* B1 = Bs + (kg + 4) * B_STRIDE;
#pragma unroll
            for (int j = 0; j < 4; j++) {
                int brow = (ng * 4 + j) * 8 + lr;
                uint32_t b0 = B0[brow];
                uint32_t b1 = B1[brow];
                mma_tf32(c[0][j], a, b0, b1);
                mma_tf32(c[1][j], a + 4, b0, b1);
            }
        }
        __syncthreads();
    }

    // epilogue: fp16 h1 (unscaled; k_starts applies dinv)
#pragma unroll
    for (int m = 0; m < 2; m++) {
        int rowa = base + mg * 32 + m * 16 + lr;
        int rowb = rowa + 8;
#pragma unroll
        for (int j = 0; j < 4; j++) {
            int col = (ng * 4 + j) * 8 + 2 * lc;
            if (rowa < NN)
                *(__half2*)&g_h1h[(size_t)rowa * FH + col] =
                    __floats2half2_rn(c[m][j][0], c[m][j][1]);
            if (rowb < NN)
                *(__half2*)&g_h1h[(size_t)rowb * FH + col] =
                    __floats2half2_rn(c[m][j][2], c[m][j][3]);
        }
    }
}

// ---------------------------------------------------------------
// gather layer 1: one warp per dst node, 4-way batching, h1 pre-scaled.
// agg1 = relu(b1 + dd*(h1'[node] + sum h1'[s]))  (fp16 out)
__global__ __launch_bounds__(256) void k_gather1(const float* __restrict__ b1) {
    int node = blockIdx.x * 8 + (threadIdx.x >> 5);
    if (node >= NN) return;
    int lane = threadIdx.x & 31;

    float dd = g_dinv[node];
    float2 sum = __half22float2(*(const __half2*)&g_h1h[(size_t)node * FH + lane * 2]);

    int beg = g_start[node];
    int end = beg + g_hist[node];
    int k = beg;
    for (; k + 3 < end; k += 4) {
        int s0 = g_csr_src[k];
        int s1 = g_csr_src[k + 1];
        int s2 = g_csr_src[k + 2];
        int s3 = g_csr_src[k + 3];
        float2 v0 = __half22float2(*(const __half2*)&g_h1h[(size_t)s0 * FH + lane * 2]);
        float2 v1 = __half22float2(*(const __half2*)&g_h1h[(size_t)s1 * FH + lane * 2]);
        float2 v2 = __half22float2(*(const __half2*)&g_h1h[(size_t)s2 * FH + lane * 2]);
        float2 v3 = __half22float2(*(const __half2*)&g_h1h[(size_t)s3 * FH + lane * 2]);
        sum.x += v0.x + v1.x + v2.x + v3.x;
        sum.y += v0.y + v1.y + v2.y + v3.y;
    }
    for (; k < end; k++) {
        int s = g_csr_src[k];
        float2 v = __half22float2(*(const __half2*)&g_h1h[(size_t)s * FH + lane * 2]);
        sum.x += v.x;
        sum.y += v.y;
    }
    float2 bb = *(const float2*)&b1[lane * 2];
    float ax = fmaxf(sum.x * dd + bb.x, 0.0f);
    float ay = fmaxf(sum.y * dd + bb.y, 0.0f);
    *(__half2*)&g_agg1h[(size_t)node * FH + lane * 2] = __floats2half2_rn(ax, ay);
}

// ---------------------------------------------------------------
// GEMM2: h2' = dinv[row] * (agg1h @ W2)  (fp16 in/out, fp32 accumulate)
__global__ __launch_bounds__(256) void k_gemm2(const float* __restrict__ W2) {
    __shared__ float Ws[FH * FC];
    for (int i = threadIdx.x; i < FH * FC; i += 256) Ws[i] = W2[i];
    __syncthreads();

    int row = blockIdx.x * 256 + threadIdx.x;
    if (row >= NN) return;

    float acc[FC];
#pragma unroll
    for (int j = 0; j < FC; j++) acc[j] = 0.0f;

    const uint4* ar = (const uint4*)&g_agg1h[(size_t)row * FH];
#pragma unroll
    for (int q = 0; q < 8; q++) {
        uint4 hv = ar[q];
        const __half2* hp = (const __half2*)&hv;
#pragma unroll
        for (int p = 0; p < 4; p++) {
            float2 f = __half22float2(hp[p]);
            int k0 = q * 8 + p * 2;
            const float4* w0 = (const float4*)&Ws[k0 * FC];
            const float4* w1 = (const float4*)&Ws[(k0 + 1) * FC];
#pragma unroll
            for (int j4 = 0; j4 < 4; j4++) {
                float4 wa = w0[j4], wb = w1[j4];
                acc[j4 * 4 + 0] += f.x * wa.x + f.y * wb.x;
                acc[j4 * 4 + 1] += f.x * wa.y + f.y * wb.y;
                acc[j4 * 4 + 2] += f.x * wa.z + f.y * wb.z;
                acc[j4 * 4 + 3] += f.x * wa.w + f.y * wb.w;
            }
        }
    }
    float dv = g_dinv[row];
    __half2 o[8];
#pragma unroll
    for (int j = 0; j < 8; j++)
        o[j] = __floats2half2_rn(acc[2 * j] * dv, acc[2 * j + 1] * dv);
    uint4* dst = (uint4*)&g_h2h[(size_t)row * FC];
    dst[0] = *(uint4*)&o[0];
    dst[1] = *(uint4*)&o[4];
}

// gather layer 2: 8 lanes per dst node, 4-way batching, h2 pre-scaled; fp32 out
__global__ __launch_bounds__(256) void k_gather2(const float* __restrict__ b2,
                                                 float* __restrict__ out) {
    int t = blockIdx.x * 256 + threadIdx.x;
    int node = t >> 3;
    if (node >= NN) return;
    int lane = t & 7;

    float dd = g_dinv[node];
    float2 sum = __half22float2(*(const __half2*)&g_h2h[(size_t)node * FC + lane * 2]);

    int beg = g_start[node];
    int end = beg + g_hist[node];
    int k = beg;
    for (; k + 3 < end; k += 4) {
        int s0 = g_csr_src[k];
        int s1 = g_csr_src[k + 1];
        int s2 = g_csr_src[k + 2];
        int s3 = g_csr_src[k + 3];
        float2 v0 = __half22float2(*(const __half2*)&g_h2h[(size_t)s0 * FC + lane * 2]);
        float2 v1 = __half22float2(*(const __half2*)&g_h2h[(size_t)s1 * FC + lane * 2]);
        float2 v2 = __half22float2(*(const __half2*)&g_h2h[(size_t)s2 * FC + lane * 2]);
        float2 v3 = __half22float2(*(const __half2*)&g_h2h[(size_t)s3 * FC + lane * 2]);
        sum.x += v0.x + v1.x + v2.x + v3.x;
        sum.y += v0.y + v1.y + v2.y + v3.y;
    }
    for (; k < end; k++) {
        int s = g_csr_src[k];
        float2 v = __half22float2(*(const __half2*)&g_h2h[(size_t)s * FC + lane * 2]);
        sum.x += v.x;
        sum.y += v.y;
    }
    float2 bb = *(const float2*)&b2[lane * 2];
    *(float2*)&out[(size_t)node * FC + lane * 2] =
        make_float2(sum.x * dd + bb.x, sum.y * dd + bb.y);
}

// ---------------------------------------------------------------
extern "C" void kernel_launch(void* const* d_in, const int* in_sizes, int n_in,
                              void* d_out, int out_size) {
    const float* x  = (const float*)d_in[0];
    const void*  ei = d_in[1];
    const float* W1 = (const float*)d_in[2];
    const float* b1 = (const float*)d_in[3];
    const float* W2 = (const float*)d_in[4];
    const float* b2 = (const float*)d_in[5];
    float* out = (float*)d_out;

    cudaFuncSetAttribute(k_gemm1, cudaFuncAttributeMaxDynamicSharedMemorySize, SM1_TOTAL);

    k_init<<<NB, 256>>>(ei);
    k_gemm1<<<G1_GRID, G1_THREADS, SM1_TOTAL>>>(x, W1, ei);   // + fused hist/rank
    k_starts<<<NB, 256>>>();                                  // + fused h1 scaling
    k_fill<<<(NE + 255) / 256, 256>>>(ei);                    // 4th -> profiled (atomic-free)
    k_gather1<<<(NN + 7) / 8, 256>>>(b1);
    k_gemm2<<<(NN + 255) / 256, 256>>>(W2);
    {
        long long threads = (long long)NN * 8;
        k_gather2<<<(unsigned)((threads + 255) / 256), 256>>>(b2, out);
    }
}

// round 14
// speedup vs baseline: 1.0846x; 1.0846x over previous
#include <cuda_runtime.h>
#include <cuda_fp16.h>
#include <cstdint>

#define NN 100000
#define NE 1600000
#define FIN 256
#define FH 64
#define FC 16
#define NB ((NN + 255) / 256)

typedef unsigned long long u64;

// ---- scratch (device globals) ----
__device__ float  g_dinv[NN];
__device__ int    g_hist[NN];
__device__ int    g_start[NN];
__device__ int    g_cursor[NN];
__device__ int    g_csr_src[NE];
__device__ int    g_alloc;
__device__ __half g_h1h[(size_t)NN * FH];     // x @ W1 (fp16)
__device__ __half g_agg1h[(size_t)NN * FH];   // relu(layer-1 out) (fp16)
__device__ __half g_h2h[(size_t)NN * FC];     // agg1 @ W2 (fp16)
__device__ int    g_is64;

// ---------------------------------------------------------------
// detect edge dtype (block 0) + zero hist (all blocks)
__global__ void k_init(const void* ei) {
    int i = blockIdx.x * blockDim.x + threadIdx.x;
    if (i < NN) g_hist[i] = 0;
    if (blockIdx.x == 0 && threadIdx.x < 32) {
        const long long* p = (const long long*)ei;
        bool bad = false;
        for (int j = threadIdx.x; j < 64; j += 32) {
            long long v = p[j];
            if (v < 0 || v >= NN) bad = true;
        }
        unsigned m = __ballot_sync(0xFFFFFFFFu, bad);
        if (threadIdx.x == 0) { g_is64 = (m == 0); g_alloc = 0; }
    }
}

// indices < 2^31: for int64 (little-endian) read only the low word
__device__ __forceinline__ int load_idx(const void* ei, int which, int e) {
    if (g_is64) return ((const int*)ei)[((size_t)which * NE + e) * 2];
    else        return ((const int*)ei)[(size_t)which * NE + e];
}

// ---- CSR offsets (atomic block base) ----
__global__ void k_starts() {
    __shared__ int sm[256];
    __shared__ int sbase;
    int t = threadIdx.x;
    int i = blockIdx.x * 256 + t;
    int h = (i < NN) ? g_hist[i] : 0;
    sm[t] = h;
    __syncthreads();
#pragma unroll
    for (int off = 1; off < 256; off <<= 1) {
        int u = (t >= off) ? sm[t - off] : 0;
        __syncthreads();
        sm[t] += u;
        __syncthreads();
    }
    if (t == 255) sbase = atomicAdd(&g_alloc, sm[255]);
    __syncthreads();
    if (i < NN) {
        int excl = sbase + sm[t] - h;
        g_start[i] = excl;
        g_cursor[i] = excl;
        g_dinv[i] = rsqrtf((float)h + 1.0f);
    }
}

// fill, 4 edges per thread (atomic MLP=4). NE % 4 == 0.
__global__ void k_fill(const void* __restrict__ ei) {
    int t = blockIdx.x * blockDim.x + threadIdx.x;
    int e0 = t * 4;
    if (e0 >= NE) return;

    int s[4], d[4];
    if (g_is64) {
        const int4* p = (const int4*)ei;          // 2 int64 per int4; low words .x/.z
        int4 a0 = p[(e0 >> 1)];
        int4 a1 = p[(e0 >> 1) + 1];
        s[0] = a0.x; s[1] = a0.z; s[2] = a1.x; s[3] = a1.z;
        const int4* pd = p + (NE >> 1);
        int4 b0 = pd[(e0 >> 1)];
        int4 b1 = pd[(e0 >> 1) + 1];
        d[0] = b0.x; d[1] = b0.z; d[2] = b1.x; d[3] = b1.z;
    } else {
        const int4* p = (const int4*)ei;
        int4 a = p[e0 >> 2];
        s[0] = a.x; s[1] = a.y; s[2] = a.z; s[3] = a.w;
        int4 b = p[(NE >> 2) + (e0 >> 2)];
        d[0] = b.x; d[1] = b.y; d[2] = b.z; d[3] = b.w;
    }

    int pos[4];
#pragma unroll
    for (int i = 0; i < 4; i++) pos[i] = atomicAdd(&g_cursor[d[i]], 1);
#pragma unroll
    for (int i = 0; i < 4; i++) g_csr_src[pos[i]] = s[i];
}

// ===================================================================
// GEMM1 (+ fused degree histogram): mma.sync tf32 (A raw fp32 = RZ),
// cp.async double-buffered; B[k][n] stride 72 (conflict-free).
// ===================================================================
#define G1_THREADS 256
#define G1_ROWS 128
#define G1_GRID ((NN + G1_ROWS - 1) / G1_ROWS)     // 782
#define EPB ((NE + G1_GRID - 1) / G1_GRID)          // 2047
#define KT 32
#define NKT (FIN / KT)
#define A_STRIDE 36
#define A_BUF_U32 (G1_ROWS * A_STRIDE)
#define B_STRIDE 72
#define B_U32 (FIN * B_STRIDE)
#define SM1_TOTAL ((2 * A_BUF_U32 + B_U32) * 4)    // 110592 -> 2 CTAs/SM

__device__ __forceinline__ uint32_t smem_u32(const void* p) {
    uint32_t a;
    asm("{ .reg .u64 t; cvta.to.shared.u64 t, %1; cvt.u32.u64 %0, t; }" : "=r"(a) : "l"(p));
    return a;
}
__device__ __forceinline__ uint32_t cvt_tf32f(float f) {
    uint32_t u;
    asm("cvt.rna.tf32.f32 %0, %1;" : "=r"(u) : "f"(f));
    return u;
}
__device__ __forceinline__ void mma_tf32(float* c, const uint32_t* a,
                                         uint32_t b0, uint32_t b1) {
    asm volatile(
        "mma.sync.aligned.m16n8k8.row.col.f32.tf32.tf32.f32 "
        "{%0,%1,%2,%3}, {%4,%5,%6,%7}, {%8,%9}, {%0,%1,%2,%3};"
        : "+f"(c[0]), "+f"(c[1]), "+f"(c[2]), "+f"(c[3])
        : "r"(a[0]), "r"(a[1]), "r"(a[2]), "r"(a[3]), "r"(b0), "r"(b1));
}

__device__ __forceinline__ void issue_tile(uint32_t dst_base, const float* __restrict__ x,
                                           int base, int kt, int tid) {
#pragma unroll
    for (int it = 0; it < 4; it++) {
        int idx = tid + it * G1_THREADS;
        int row = idx >> 3;
        int c4 = idx & 7;
        int gr = base + row;
        int ok = (gr < NN) ? 16 : 0;
        int gs = (gr < NN) ? gr : (NN - 1);
        const float* src = x + (size_t)gs * FIN + kt * KT + c4 * 4;
        uint32_t dst = dst_base + row * (A_STRIDE * 4) + c4 * 16;
        asm volatile("cp.async.ca.shared.global [%0], [%1], 16, %2;"
                     :: "r"(dst), "l"(src), "r"(ok) : "memory");
    }
    asm volatile("cp.async.commit_group;" ::: "memory");
}

__global__ void __launch_bounds__(G1_THREADS, 2) k_gemm1(const float* __restrict__ x,
                                                         const float* __restrict__ W1,
                                                         const void* __restrict__ ei) {
    extern __shared__ uint32_t smem[];
    uint32_t* As = smem;
    uint32_t* Bs = smem + 2 * A_BUF_U32;
    uint32_t asu = smem_u32(As);

    int tid = threadIdx.x;
    int w = tid >> 5;
    int lane = tid & 31;
    int lr = lane >> 2;
    int lc = lane & 3;
    int mg = w & 3;
    int ng = w >> 2;
    int base = blockIdx.x * G1_ROWS;

    issue_tile(asu, x, base, 0, tid);

    // fused degree histogram (fire-and-forget REDG)
    {
        int ebeg = blockIdx.x * EPB;
        int eend = min(ebeg + EPB, NE);
        for (int e = ebeg + tid; e < eend; e += G1_THREADS) {
            int d = load_idx(ei, 1, e);
            atomicAdd(&g_hist[d], 1);
        }
    }

    // stage B: W1[k][n] -> Bs[k*72 + n], STS.128 conflict-free
    {
        const float4* w4 = (const float4*)W1;
#pragma unroll
        for (int it = 0; it < 16; it++) {
            int idx = tid + it * G1_THREADS;
            int k = idx >> 4;
            int n4 = idx & 15;
            float4 v = w4[idx];
            uint4 t;
            t.x = cvt_tf32f(v.x); t.y = cvt_tf32f(v.y);
            t.z = cvt_tf32f(v.z); t.w = cvt_tf32f(v.w);
            *(uint4*)&Bs[k * B_STRIDE + n4 * 4] = t;
        }
    }

    float c[2][4][4];
#pragma unroll
    for (int m = 0; m < 2; m++)
#pragma unroll
        for (int j = 0; j < 4; j++)
#pragma unroll
            for (int i = 0; i < 4; i++) c[m][j][i] = 0.0f;

    int ar = mg * 32 + lr;

#pragma unroll
    for (int kt = 0; kt < NKT; kt++) {
        if (kt + 1 < NKT) {
            issue_tile(asu + ((kt + 1) & 1) * (A_BUF_U32 * 4), x, base, kt + 1, tid);
            asm volatile("cp.async.wait_group 1;" ::: "memory");
        } else {
            asm volatile("cp.async.wait_group 0;" ::: "memory");
        }
        __syncthreads();

        const uint32_t* A = As + (kt & 1) * A_BUF_U32;
#pragma unroll
        for (int ks = 0; ks < 4; ks++) {
            int kk = ks * 8 + lc;
            uint32_t a[8];
            a[0] = A[(ar)      * A_STRIDE + kk];
            a[1] = A[(ar + 8)  * A_STRIDE + kk];
            a[2] = A[(ar)      * A_STRIDE + kk + 4];
            a[3] = A[(ar + 8)  * A_STRIDE + kk + 4];
            a[4] = A[(ar + 16) * A_STRIDE + kk];
            a[5] = A[(ar + 24) * A_STRIDE + kk];
            a[6] = A[(ar + 16) * A_STRIDE + kk + 4];
            a[7] = A[(ar + 24) * A_STRIDE + kk + 4];
            int kg = kt * KT + ks * 8 + lc;
            const uint32_t* B0 = Bs + kg * B_STRIDE;
            const uint32_t* B1 = Bs + (kg + 4) * B_STRIDE;
#pragma unroll
            for (int j = 0; j < 4; j++) {
                int brow = (ng * 4 + j) * 8 + lr;
                uint32_t b0 = B0[brow];
                uint32_t b1 = B1[brow];
                mma_tf32(c[0][j], a, b0, b1);
                mma_tf32(c[1][j], a + 4, b0, b1);
            }
        }
        __syncthreads();
    }

    // epilogue: fp16 h1
#pragma unroll
    for (int m = 0; m < 2; m++) {
        int rowa = base + mg * 32 + m * 16 + lr;
        int rowb = rowa + 8;
#pragma unroll
        for (int j = 0; j < 4; j++) {
            int col = (ng * 4 + j) * 8 + 2 * lc;
            if (rowa < NN)
                *(__half2*)&g_h1h[(size_t)rowa * FH + col] =
                    __floats2half2_rn(c[m][j][0], c[m][j][1]);
            if (rowb < NN)
                *(__half2*)&g_h1h[(size_t)rowb * FH + col] =
                    __floats2half2_rn(c[m][j][2], c[m][j][3]);
        }
    }
}

// ---------------------------------------------------------------
// gather layer 1: one warp per dst node; 4-way edge batching (MLP).
// agg1 = relu(b1 + dd*sum(dinv[s]*h1[s]) + d2*h1[node])  (fp16 out)
__global__ __launch_bounds__(256) void k_gather1(const float* __restrict__ b1) {
    int node = blockIdx.x * 8 + (threadIdx.x >> 5);
    if (node >= NN) return;
    int lane = threadIdx.x & 31;

    float dd = g_dinv[node];
    float d2 = dd * dd;
    float2 self = __half22float2(*(const __half2*)&g_h1h[(size_t)node * FH + lane * 2]);

    float2 sum = make_float2(0.f, 0.f);
    int beg = g_start[node];
    int end = beg + g_hist[node];
    int k = beg;
    for (; k + 3 < end; k += 4) {
        int s0 = g_csr_src[k];
        int s1 = g_csr_src[k + 1];
        int s2 = g_csr_src[k + 2];
        int s3 = g_csr_src[k + 3];
        float n0 = g_dinv[s0], n1 = g_dinv[s1], n2 = g_dinv[s2], n3 = g_dinv[s3];
        float2 v0 = __half22float2(*(const __half2*)&g_h1h[(size_t)s0 * FH + lane * 2]);
        float2 v1 = __half22float2(*(const __half2*)&g_h1h[(size_t)s1 * FH + lane * 2]);
        float2 v2 = __half22float2(*(const __half2*)&g_h1h[(size_t)s2 * FH + lane * 2]);
        float2 v3 = __half22float2(*(const __half2*)&g_h1h[(size_t)s3 * FH + lane * 2]);
        sum.x += v0.x * n0 + v1.x * n1 + v2.x * n2 + v3.x * n3;
        sum.y += v0.y * n0 + v1.y * n1 + v2.y * n2 + v3.y * n3;
    }
    for (; k < end; k++) {
        int s = g_csr_src[k];
        float n = g_dinv[s];
        float2 v = __half22float2(*(const __half2*)&g_h1h[(size_t)s * FH + lane * 2]);
        sum.x += v.x * n;
        sum.y += v.y * n;
    }
    float2 bb = *(const float2*)&b1[lane * 2];
    float ax = fmaxf(self.x * d2 + sum.x * dd + bb.x, 0.0f);
    float ay = fmaxf(self.y * d2 + sum.y * dd + bb.y, 0.0f);
    *(__half2*)&g_agg1h[(size_t)node * FH + lane * 2] = __floats2half2_rn(ax, ay);
}

// ---------------------------------------------------------------
// GEMM2: h2 = agg1h @ W2[64,16]  (fp16 in/out, fp32 accumulate)
__global__ __launch_bounds__(256) void k_gemm2(const float* __restrict__ W2) {
    __shared__ float Ws[FH * FC];
    for (int i = threadIdx.x; i < FH * FC; i += 256) Ws[i] = W2[i];
    __syncthreads();

    int row = blockIdx.x * 256 + threadIdx.x;
    if (row >= NN) return;

    float acc[FC];
#pragma unroll
    for (int j = 0; j < FC; j++) acc[j] = 0.0f;

    const uint4* ar = (const uint4*)&g_agg1h[(size_t)row * FH];
#pragma unroll
    for (int q = 0; q < 8; q++) {
        uint4 hv = ar[q];
        const __half2* hp = (const __half2*)&hv;
#pragma unroll
        for (int p = 0; p < 4; p++) {
            float2 f = __half22float2(hp[p]);
            int k0 = q * 8 + p * 2;
            const float4* w0 = (const float4*)&Ws[k0 * FC];
            const float4* w1 = (const float4*)&Ws[(k0 + 1) * FC];
#pragma unroll
            for (int j4 = 0; j4 < 4; j4++) {
                float4 wa = w0[j4], wb = w1[j4];
                acc[j4 * 4 + 0] += f.x * wa.x + f.y * wb.x;
                acc[j4 * 4 + 1] += f.x * wa.y + f.y * wb.y;
                acc[j4 * 4 + 2] += f.x * wa.z + f.y * wb.z;
                acc[j4 * 4 + 3] += f.x * wa.w + f.y * wb.w;
            }
        }
    }
    __half2 o[8];
#pragma unroll
    for (int j = 0; j < 8; j++) o[j] = __floats2half2_rn(acc[2 * j], acc[2 * j + 1]);
    uint4* dst = (uint4*)&g_h2h[(size_t)row * FC];
    dst[0] = *(uint4*)&o[0];
    dst[1] = *(uint4*)&o[4];
}

// gather layer 2: 8 lanes per dst node, 4-way edge batching; fp32 out
__global__ __launch_bounds__(256) void k_gather2(const float* __restrict__ b2,
                                                 float* __restrict__ out) {
    int t = blockIdx.x * 256 + threadIdx.x;
    int node = t >> 3;
    if (node >= NN) return;
    int lane = t & 7;

    float dd = g_dinv[node];
    float d2 = dd * dd;
    float2 self = __half22float2(*(const __half2*)&g_h2h[(size_t)node * FC + lane * 2]);

    float2 sum = make_float2(0.f, 0.f);
    int beg = g_start[node];
    int end = beg + g_hist[node];
    int k = beg;
    for (; k + 3 < end; k += 4) {
        int s0 = g_csr_src[k];
        int s1 = g_csr_src[k + 1];
        int s2 = g_csr_src[k + 2];
        int s3 = g_csr_src[k + 3];
        float n0 = g_dinv[s0], n1 = g_dinv[s1], n2 = g_dinv[s2], n3 = g_dinv[s3];
        float2 v0 = __half22float2(*(const __half2*)&g_h2h[(size_t)s0 * FC + lane * 2]);
        float2 v1 = __half22float2(*(const __half2*)&g_h2h[(size_t)s1 * FC + lane * 2]);
        float2 v2 = __half22float2(*(const __half2*)&g_h2h[(size_t)s2 * FC + lane * 2]);
        float2 v3 = __half22float2(*(const __half2*)&g_h2h[(size_t)s3 * FC + lane * 2]);
        sum.x += v0.x * n0 + v1.x * n1 + v2.x * n2 + v3.x * n3;
        sum.y += v0.y * n0 + v1.y * n1 + v2.y * n2 + v3.y * n3;
    }
    for (; k < end; k++) {
        int s = g_csr_src[k];
        float n = g_dinv[s];
        float2 v = __half22float2(*(const __half2*)&g_h2h[(size_t)s * FC + lane * 2]);
        sum.x += v.x * n;
        sum.y += v.y * n;
    }
    float2 bb = *(const float2*)&b2[lane * 2];
    *(float2*)&out[(size_t)node * FC + lane * 2] =
        make_float2(self.x * d2 + sum.x * dd + bb.x,
                    self.y * d2 + sum.y * dd + bb.y);
}

// ---------------------------------------------------------------
extern "C" void kernel_launch(void* const* d_in, const int* in_sizes, int n_in,
                              void* d_out, int out_size) {
    const float* x  = (const float*)d_in[0];
    const void*  ei = d_in[1];
    const float* W1 = (const float*)d_in[2];
    const float* b1 = (const float*)d_in[3];
    const float* W2 = (const float*)d_in[4];
    const float* b2 = (const float*)d_in[5];
    float* out = (float*)d_out;

    cudaFuncSetAttribute(k_gemm1, cudaFuncAttributeMaxDynamicSharedMemorySize, SM1_TOTAL);

    k_init<<<NB, 256>>>(ei);
    k_gemm1<<<G1_GRID, G1_THREADS, SM1_TOTAL>>>(x, W1, ei);   // + fused hist
    k_starts<<<NB, 256>>>();
    k_fill<<<(NE / 4 + 255) / 256, 256>>>(ei);                // 4th -> profiled (4 edges/thread)
    k_gather1<<<(NN + 7) / 8, 256>>>(b1);
    k_gemm2<<<(NN + 255) / 256, 256>>>(W2);
    {
        long long threads = (long long)NN * 8;
        k_gather2<<<(unsigned)((threads + 255) / 256), 256>>>(b2, out);
    }
}

// round 15
// speedup vs baseline: 1.1165x; 1.0294x over previous
#include <cuda_runtime.h>
#include <cuda_fp16.h>
#include <cstdint>

#define NN 100000
#define NE 1600000
#define FIN 256
#define FH 64
#define FC 16
#define NB ((NN + 255) / 256)

typedef unsigned long long u64;

// ---- scratch (device globals) ----
__device__ float  g_dinv[NN];
__device__ int    g_hist[NN];
__device__ int    g_start[NN];
__device__ int    g_cursor[NN];
__device__ int    g_csr_src[NE];
__device__ int    g_alloc;
__device__ __half g_h1h[(size_t)NN * FH];     // x @ W1 (fp16)
__device__ __half g_agg1h[(size_t)NN * FH];   // relu(layer-1 out) (fp16)
__device__ __half g_h2h[(size_t)NN * FC];     // agg1 @ W2 (fp16)
__device__ int    g_is64;

// ---------------------------------------------------------------
__global__ void k_init(const void* ei) {
    int i = blockIdx.x * blockDim.x + threadIdx.x;
    if (i < NN) g_hist[i] = 0;
    if (blockIdx.x == 0 && threadIdx.x < 32) {
        const long long* p = (const long long*)ei;
        bool bad = false;
        for (int j = threadIdx.x; j < 64; j += 32) {
            long long v = p[j];
            if (v < 0 || v >= NN) bad = true;
        }
        unsigned m = __ballot_sync(0xFFFFFFFFu, bad);
        if (threadIdx.x == 0) { g_is64 = (m == 0); g_alloc = 0; }
    }
}

// indices < 2^31: for int64 (little-endian) read only the low word
__device__ __forceinline__ int load_idx(const void* ei, int which, int e) {
    if (g_is64) return ((const int*)ei)[((size_t)which * NE + e) * 2];
    else        return ((const int*)ei)[(size_t)which * NE + e];
}

// ---- CSR offsets (atomic block base) ----
__global__ void k_starts() {
    __shared__ int sm[256];
    __shared__ int sbase;
    int t = threadIdx.x;
    int i = blockIdx.x * 256 + t;
    int h = (i < NN) ? g_hist[i] : 0;
    sm[t] = h;
    __syncthreads();
#pragma unroll
    for (int off = 1; off < 256; off <<= 1) {
        int u = (t >= off) ? sm[t - off] : 0;
        __syncthreads();
        sm[t] += u;
        __syncthreads();
    }
    if (t == 255) sbase = atomicAdd(&g_alloc, sm[255]);
    __syncthreads();
    if (i < NN) {
        int excl = sbase + sm[t] - h;
        g_start[i] = excl;
        g_cursor[i] = excl;
        g_dinv[i] = rsqrtf((float)h + 1.0f);
    }
}

__global__ void k_fill(const void* __restrict__ ei) {
    int e = blockIdx.x * blockDim.x + threadIdx.x;
    if (e >= NE) return;
    int s = load_idx(ei, 0, e);
    int d = load_idx(ei, 1, e);
    int pos = atomicAdd(&g_cursor[d], 1);
    g_csr_src[pos] = s;
}

// ===================================================================
// GEMM1 (+ fused degree histogram): mma.sync tf32 (A raw fp32 = RZ),
// 3-stage cp.async pipeline (prefetch distance 2), 512 threads,
// M=256 rows/CTA, 1 CTA/SM. B[k][n] stride 72 (conflict-free).
// ===================================================================
#define G1_THREADS 512
#define G1_ROWS 256
#define G1_GRID ((NN + G1_ROWS - 1) / G1_ROWS)     // 391
#define EPB ((NE + G1_GRID - 1) / G1_GRID)          // 4092
#define KT 32
#define NKT (FIN / KT)                              // 8
#define A_STRIDE 36
#define A_BUF_U32 (G1_ROWS * A_STRIDE)              // 9216 u32 = 36KB
#define B_STRIDE 72
#define B_U32 (FIN * B_STRIDE)                      // 18432 u32 = 72KB
#define SM1_TOTAL ((3 * A_BUF_U32 + B_U32) * 4)     // 184320 B -> 1 CTA/SM

__device__ __forceinline__ uint32_t smem_u32(const void* p) {
    uint32_t a;
    asm("{ .reg .u64 t; cvta.to.shared.u64 t, %1; cvt.u32.u64 %0, t; }" : "=r"(a) : "l"(p));
    return a;
}
__device__ __forceinline__ uint32_t cvt_tf32f(float f) {
    uint32_t u;
    asm("cvt.rna.tf32.f32 %0, %1;" : "=r"(u) : "f"(f));
    return u;
}
__device__ __forceinline__ void mma_tf32(float* c, const uint32_t* a,
                                         uint32_t b0, uint32_t b1) {
    asm volatile(
        "mma.sync.aligned.m16n8k8.row.col.f32.tf32.tf32.f32 "
        "{%0,%1,%2,%3}, {%4,%5,%6,%7}, {%8,%9}, {%0,%1,%2,%3};"
        : "+f"(c[0]), "+f"(c[1]), "+f"(c[2]), "+f"(c[3])
        : "r"(a[0]), "r"(a[1]), "r"(a[2]), "r"(a[3]), "r"(b0), "r"(b1));
}

// stage one K-tile of A (256 rows x 32 cols fp32) via cp.async
__device__ __forceinline__ void issue_tile(uint32_t dst_base, const float* __restrict__ x,
                                           int base, int kt, int tid) {
#pragma unroll
    for (int it = 0; it < 4; it++) {
        int idx = tid + it * G1_THREADS;       // 0..2047
        int row = idx >> 3;
        int c4 = idx & 7;
        int gr = base + row;
        int ok = (gr < NN) ? 16 : 0;
        int gs = (gr < NN) ? gr : (NN - 1);
        const float* src = x + (size_t)gs * FIN + kt * KT + c4 * 4;
        uint32_t dst = dst_base + row * (A_STRIDE * 4) + c4 * 16;
        asm volatile("cp.async.ca.shared.global [%0], [%1], 16, %2;"
                     :: "r"(dst), "l"(src), "r"(ok) : "memory");
    }
    asm volatile("cp.async.commit_group;" ::: "memory");
}

__global__ void __launch_bounds__(G1_THREADS, 1) k_gemm1(const float* __restrict__ x,
                                                         const float* __restrict__ W1,
                                                         const void* __restrict__ ei) {
    extern __shared__ uint32_t smem[];
    uint32_t* As = smem;                    // [3][256][A_STRIDE]
    uint32_t* Bs = smem + 3 * A_BUF_U32;    // [256][B_STRIDE]: tf32(W1[k][n])
    uint32_t asu = smem_u32(As);

    int tid = threadIdx.x;
    int w = tid >> 5;
    int lane = tid & 31;
    int lr = lane >> 2;
    int lc = lane & 3;
    int mg = w & 7;            // 8 m-groups of 32 rows
    int ng = w >> 3;           // 2 n-groups of 32 cols
    int base = blockIdx.x * G1_ROWS;

    issue_tile(asu, x, base, 0, tid);                      // tile 0
    issue_tile(asu + A_BUF_U32 * 4, x, base, 1, tid);      // tile 1

    // fused degree histogram (fire-and-forget REDG), overlapped with loads
    {
        int ebeg = blockIdx.x * EPB;
        int eend = min(ebeg + EPB, NE);
        for (int e = ebeg + tid; e < eend; e += G1_THREADS) {
            int d = load_idx(ei, 1, e);
            atomicAdd(&g_hist[d], 1);
        }
    }

    // stage B: W1[k][n] -> Bs[k*72 + n], STS.128 conflict-free
    {
        const float4* w4 = (const float4*)W1;
#pragma unroll
        for (int it = 0; it < 8; it++) {
            int idx = tid + it * G1_THREADS;   // 4096 float4s
            int k = idx >> 4;
            int n4 = idx & 15;
            float4 v = w4[idx];
            uint4 t;
            t.x = cvt_tf32f(v.x); t.y = cvt_tf32f(v.y);
            t.z = cvt_tf32f(v.z); t.w = cvt_tf32f(v.w);
            *(uint4*)&Bs[k * B_STRIDE + n4 * 4] = t;
        }
    }

    float c[2][4][4];
#pragma unroll
    for (int m = 0; m < 2; m++)
#pragma unroll
        for (int j = 0; j < 4; j++)
#pragma unroll
            for (int i = 0; i < 4; i++) c[m][j][i] = 0.0f;

    int ar = mg * 32 + lr;

#pragma unroll
    for (int kt = 0; kt < NKT; kt++) {
        // prefetch distance 2 (3 buffers). Buf[(kt+2)%3] was consumed at kt-1.
        if (kt + 2 < NKT)
            issue_tile(asu + ((kt + 2) % 3) * (A_BUF_U32 * 4), x, base, kt + 2, tid);

        // tile kt ready when pending groups <= #groups issued after it
        if (kt + 2 < NKT)      asm volatile("cp.async.wait_group 2;" ::: "memory");
        else if (kt + 1 < NKT) asm volatile("cp.async.wait_group 1;" ::: "memory");
        else                   asm volatile("cp.async.wait_group 0;" ::: "memory");
        __syncthreads();

        const uint32_t* A = As + (kt % 3) * A_BUF_U32;
#pragma unroll
        for (int ks = 0; ks < 4; ks++) {
            int kk = ks * 8 + lc;
            uint32_t a[8];
            a[0] = A[(ar)      * A_STRIDE + kk];
            a[1] = A[(ar + 8)  * A_STRIDE + kk];
            a[2] = A[(ar)      * A_STRIDE + kk + 4];
            a[3] = A[(ar + 8)  * A_STRIDE + kk + 4];
            a[4] = A[(ar + 16) * A_STRIDE + kk];
            a[5] = A[(ar + 24) * A_STRIDE + kk];
            a[6] = A[(ar + 16) * A_STRIDE + kk + 4];
            a[7] = A[(ar + 24) * A_STRIDE + kk + 4];
            int kg = kt * KT + ks * 8 + lc;
            const uint32_t* B0 = Bs + kg * B_STRIDE;
            const uint32_t* B1 = Bs + (kg + 4) * B_STRIDE;
#pragma unroll
            for (int j = 0; j < 4; j++) {
                int brow = (ng * 4 + j) * 8 + lr;
                uint32_t b0 = B0[brow];
                uint32_t b1 = B1[brow];
                mma_tf32(c[0][j], a, b0, b1);
                mma_tf32(c[1][j], a + 4, b0, b1);
            }
        }
        __syncthreads();
    }

    // epilogue: fp16 h1
#pragma unroll
    for (int m = 0; m < 2; m++) {
        int rowa = base + mg * 32 + m * 16 + lr;
        int rowb = rowa + 8;
#pragma unroll
        for (int j = 0; j < 4; j++) {
            int col = (ng * 4 + j) * 8 + 2 * lc;
            if (rowa < NN)
                *(__half2*)&g_h1h[(size_t)rowa * FH + col] =
                    __floats2half2_rn(c[m][j][0], c[m][j][1]);
            if (rowb < NN)
                *(__half2*)&g_h1h[(size_t)rowb * FH + col] =
                    __floats2half2_rn(c[m][j][2], c[m][j][3]);
        }
    }
}

// ---------------------------------------------------------------
// gather layer 1: one warp per dst node; 4-way edge batching.
__global__ __launch_bounds__(256) void k_gather1(const float* __restrict__ b1) {
    int node = blockIdx.x * 8 + (threadIdx.x >> 5);
    if (node >= NN) return;
    int lane = threadIdx.x & 31;

    float dd = g_dinv[node];
    float d2 = dd * dd;
    float2 self = __half22float2(*(const __half2*)&g_h1h[(size_t)node * FH + lane * 2]);

    float2 sum = make_float2(0.f, 0.f);
    int beg = g_start[node];
    int end = beg + g_hist[node];
    int k = beg;
    for (; k + 3 < end; k += 4) {
        int s0 = g_csr_src[k];
        int s1 = g_csr_src[k + 1];
        int s2 = g_csr_src[k + 2];
        int s3 = g_csr_src[k + 3];
        float n0 = g_dinv[s0], n1 = g_dinv[s1], n2 = g_dinv[s2], n3 = g_dinv[s3];
        float2 v0 = __half22float2(*(const __half2*)&g_h1h[(size_t)s0 * FH + lane * 2]);
        float2 v1 = __half22float2(*(const __half2*)&g_h1h[(size_t)s1 * FH + lane * 2]);
        float2 v2 = __half22float2(*(const __half2*)&g_h1h[(size_t)s2 * FH + lane * 2]);
        float2 v3 = __half22float2(*(const __half2*)&g_h1h[(size_t)s3 * FH + lane * 2]);
        sum.x += v0.x * n0 + v1.x * n1 + v2.x * n2 + v3.x * n3;
        sum.y += v0.y * n0 + v1.y * n1 + v2.y * n2 + v3.y * n3;
    }
    for (; k < end; k++) {
        int s = g_csr_src[k];
        float n = g_dinv[s];
        float2 v = __half22float2(*(const __half2*)&g_h1h[(size_t)s * FH + lane * 2]);
        sum.x += v.x * n;
        sum.y += v.y * n;
    }
    float2 bb = *(const float2*)&b1[lane * 2];
    float ax = fmaxf(self.x * d2 + sum.x * dd + bb.x, 0.0f);
    float ay = fmaxf(self.y * d2 + sum.y * dd + bb.y, 0.0f);
    *(__half2*)&g_agg1h[(size_t)node * FH + lane * 2] = __floats2half2_rn(ax, ay);
}

// ---------------------------------------------------------------
// GEMM2: h2 = agg1h @ W2[64,16]  (fp16 in/out, fp32 accumulate)
__global__ __launch_bounds__(256) void k_gemm2(const float* __restrict__ W2) {
    __shared__ float Ws[FH * FC];
    for (int i = threadIdx.x; i < FH * FC; i += 256) Ws[i] = W2[i];
    __syncthreads();

    int row = blockIdx.x * 256 + threadIdx.x;
    if (row >= NN) return;

    float acc[FC];
#pragma unroll
    for (int j = 0; j < FC; j++) acc[j] = 0.0f;

    const uint4* ar = (const uint4*)&g_agg1h[(size_t)row * FH];
#pragma unroll
    for (int q = 0; q < 8; q++) {
        uint4 hv = ar[q];
        const __half2* hp = (const __half2*)&hv;
#pragma unroll
        for (int p = 0; p < 4; p++) {
            float2 f = __half22float2(hp[p]);
            int k0 = q * 8 + p * 2;
            const float4* w0 = (const float4*)&Ws[k0 * FC];
            const float4* w1 = (const float4*)&Ws[(k0 + 1) * FC];
#pragma unroll
            for (int j4 = 0; j4 < 4; j4++) {
                float4 wa = w0[j4], wb = w1[j4];
                acc[j4 * 4 + 0] += f.x * wa.x + f.y * wb.x;
                acc[j4 * 4 + 1] += f.x * wa.y + f.y * wb.y;
                acc[j4 * 4 + 2] += f.x * wa.z + f.y * wb.z;
                acc[j4 * 4 + 3] += f.x * wa.w + f.y * wb.w;
            }
        }
    }
    __half2 o[8];
#pragma unroll
    for (int j = 0; j < 8; j++) o[j] = __floats2half2_rn(acc[2 * j], acc[2 * j + 1]);
    uint4* dst = (uint4*)&g_h2h[(size_t)row * FC];
    dst[0] = *(uint4*)&o[0];
    dst[1] = *(uint4*)&o[4];
}

// gather layer 2: 8 lanes per dst node, 4-way edge batching; fp32 out
__global__ __launch_bounds__(256) void k_gather2(const float* __restrict__ b2,
                                                 float* __restrict__ out) {
    int t = blockIdx.x * 256 + threadIdx.x;
    int node = t >> 3;
    if (node >= NN) return;
    int lane = t & 7;

    float dd = g_dinv[node];
    float d2 = dd * dd;
    float2 self = __half22float2(*(const __half2*)&g_h2h[(size_t)node * FC + lane * 2]);

    float2 sum = make_float2(0.f, 0.f);
    int beg = g_start[node];
    int end = beg + g_hist[node];
    int k = beg;
    for (; k + 3 < end; k += 4) {
        int s0 = g_csr_src[k];
        int s1 = g_csr_src[k + 1];
        int s2 = g_csr_src[k + 2];
        int s3 = g_csr_src[k + 3];
        float n0 = g_dinv[s0], n1 = g_dinv[s1], n2 = g_dinv[s2], n3 = g_dinv[s3];
        float2 v0 = __half22float2(*(const __half2*)&g_h2h[(size_t)s0 * FC + lane * 2]);
        float2 v1 = __half22float2(*(const __half2*)&g_h2h[(size_t)s1 * FC + lane * 2]);
        float2 v2 = __half22float2(*(const __half2*)&g_h2h[(size_t)s2 * FC + lane * 2]);
        float2 v3 = __half22float2(*(const __half2*)&g_h2h[(size_t)s3 * FC + lane * 2]);
        sum.x += v0.x * n0 + v1.x * n1 + v2.x * n2 + v3.x * n3;
        sum.y += v0.y * n0 + v1.y * n1 + v2.y * n2 + v3.y * n3;
    }
    for (; k < end; k++) {
        int s = g_csr_src[k];
        float n = g_dinv[s];
        float2 v = __half22float2(*(const __half2*)&g_h2h[(size_t)s * FC + lane * 2]);
        sum.x += v.x * n;
        sum.y += v.y * n;
    }
    float2 bb = *(const float2*)&b2[lane * 2];
    *(float2*)&out[(size_t)node * FC + lane * 2] =
        make_float2(self.x * d2 + sum.x * dd + bb.x,
                    self.y * d2 + sum.y * dd + bb.y);
}

// ---------------------------------------------------------------
extern "C" void kernel_launch(void* const* d_in, const int* in_sizes, int n_in,
                              void* d_out, int out_size) {
    const float* x  = (const float*)d_in[0];
    const void*  ei = d_in[1];
    const float* W1 = (const float*)d_in[2];
    const float* b1 = (const float*)d_in[3];
    const float* W2 = (const float*)d_in[4];
    const float* b2 = (const float*)d_in[5];
    float* out = (float*)d_out;

    cudaFuncSetAttribute(k_gemm1, cudaFuncAttributeMaxDynamicSharedMemorySize, SM1_TOTAL);

    k_init<<<NB, 256>>>(ei);
    k_gemm1<<<G1_GRID, G1_THREADS, SM1_TOTAL>>>(x, W1, ei);   // + fused hist
    k_starts<<<NB, 256>>>();
    k_fill<<<(NE + 255) / 256, 256>>>(ei);                    // 4th -> profiled
    k_gather1<<<(NN + 7) / 8, 256>>>(b1);
    k_gemm2<<<(NN + 255) / 256, 256>>>(W2);
    {
        long long threads = (long long)NN * 8;
        k_gather2<<<(unsigned)((threads + 255) / 256), 256>>>(b2, out);
    }
}